// round 15
// baseline (speedup 1.0000x reference)
#include <cuda_runtime.h>
#include <math.h>

#define Nn   50000
#define Ee   1600000
#define Dh   64
#define Din  128
#define Gg   64
#define NCLS 10
#define NBLK 49              // ceil(Nn/1024)
#define GEMM1_BLOCKS 782     // ceil(Nn/64)
#define SCAT_BLOCKS  6250    // ceil(Ee/256)
#define COUNT_BLOCKS 1024
#define FULLMASK 0xffffffffu

// ---------------- scratch (device globals; referenced ONLY in device code) ----------
__device__ float g_xl[Nn * Dh];      // pair-interleaved: slot 2l,2l+1 = dims l, l+32
__device__ float g_xr[Nn * Dh];
__device__ float g_h [Nn * Dh];
__device__ int   g_deg[Nn];          // zero at entry; scan re-zeroes after reading
__device__ int   g_indptr[Nn + 1];
__device__ int   g_wpos[Nn];
__device__ int2  g_csr[Ee];          // {src, attr-as-int}
__device__ float g_asum[COUNT_BLOCKS];
__device__ float g_attrsum;
__device__ float g_pooled[Gg * Dh];
__device__ int   g_cnt[Gg];
__device__ volatile int g_flag[NBLK];
__device__ volatile int g_aggr[NBLK];
__device__ volatile int g_pref[NBLK];
// pre-permuted weights (pair-interleaved columns; layer-2 rows in storage order)
__device__ float g_pwl1[Din * Dh], g_pwr1[Din * Dh];
__device__ float g_pwl2[Dh * Dh],  g_pwr2[Dh * Dh];
__device__ float g_pwe[2 * 64], g_patt[2 * 64], g_pbias[2 * 64];

// ---------------- f32x2 helpers ----------------
__device__ __forceinline__ unsigned long long pack2(float x, float y) {
    unsigned long long r;
    asm("mov.b64 %0, {%1, %2};" : "=l"(r) : "f"(x), "f"(y));
    return r;
}
__device__ __forceinline__ void fma2(unsigned long long& d, unsigned long long a,
                                     unsigned long long b) {
    asm("fma.rn.f32x2 %0, %1, %2, %3;" : "=l"(d) : "l"(a), "l"(b), "l"(d));
}
__device__ __forceinline__ unsigned long long fma2v(unsigned long long a,
                                                    unsigned long long b,
                                                    unsigned long long c) {
    unsigned long long r;
    asm("fma.rn.f32x2 %0, %1, %2, %3;" : "=l"(r) : "l"(a), "l"(b), "l"(c));
    return r;
}
__device__ __forceinline__ unsigned long long add2(unsigned long long a,
                                                   unsigned long long b) {
    unsigned long long r;
    asm("add.rn.f32x2 %0, %1, %2;" : "=l"(r) : "l"(a), "l"(b));
    return r;
}
__device__ __forceinline__ float2 unpack2(unsigned long long v) {
    float2 r;
    asm("mov.b64 {%0, %1}, %2;" : "=f"(r.x), "=f"(r.y) : "l"(v));
    return r;
}

// ------- initA: zero CSR-side scratch + degree count (branch A root) ---------------
__global__ void initA_kernel(const int* __restrict__ dst, const float* __restrict__ attr) {
    int b = blockIdx.x, t = threadIdx.x;
    if (b < 196) {
        int i = b * 256 + t;
        if (i < Gg * Dh) g_pooled[i] = 0.f;
        if (i < Gg) g_cnt[i] = 0;
        if (i < NBLK) g_flag[i] = 0;
        if (i == 0) g_indptr[Nn] = Ee;
        return;
    }
    // count part: grid-strided over edges; partial attr sums into g_asum
    int cb = b - 196;
    float v = 0.f;
    for (int e = cb * 256 + t; e < Ee; e += COUNT_BLOCKS * 256) {
        atomicAdd(&g_deg[dst[e]], 1);
        v += attr[e];
    }
    #pragma unroll
    for (int o = 16; o; o >>= 1) v += __shfl_xor_sync(FULLMASK, v, o);
    __shared__ float red[8];
    int lane = t & 31, wid = t >> 5;
    if (lane == 0) red[wid] = v;
    __syncthreads();
    if (t < 8) {
        float w = red[t];
        #pragma unroll
        for (int o = 4; o; o >>= 1) w += __shfl_xor_sync(0xffu, w, o);
        if (t == 0) g_asum[cb] = w;
    }
}

// ------- initB: weight / vector permutation (branch B root) ------------------------
__global__ void initB_kernel(const float* __restrict__ Wl1, const float* __restrict__ Wr1,
                             const float* __restrict__ Wl2, const float* __restrict__ Wr2,
                             const float* __restrict__ We1, const float* __restrict__ att1,
                             const float* __restrict__ b1,
                             const float* __restrict__ We2, const float* __restrict__ att2,
                             const float* __restrict__ b2) {
    int b = blockIdx.x, t = threadIdx.x;
    if (b < 48) {
        int idx = b * 256 + t;                        // 48*256 = 12288 = Din*Dh + Dh*Dh
        if (idx < Din * Dh) {                         // layer-1 weights [128][64]
            int k = idx >> 6, d = idx & 63;
            int st = 2 * (d & 31) + (d >> 5);
            g_pwl1[k * 64 + st] = Wl1[idx];
            g_pwr1[k * 64 + st] = Wr1[idx];
        } else {                                      // layer-2 weights [64][64]
            int j = idx - Din * Dh;
            int k = j >> 6, d = j & 63;
            int srow = 2 * (k & 31) + (k >> 5);       // input rows in storage order
            int st   = 2 * (d & 31) + (d >> 5);
            g_pwl2[srow * 64 + st] = Wl2[j];
            g_pwr2[srow * 64 + st] = Wr2[j];
        }
        return;
    }
    if (t < 128) {
        int L = t >> 6, s = t & 63;
        int d = (s >> 1) + ((s & 1) << 5);            // storage slot -> true dim
        const float* We = L ? We2 : We1;
        const float* at = L ? att2 : att1;
        const float* bi = L ? b2  : b1;
        g_pwe  [L * 64 + s] = We[d];
        g_patt [L * 64 + s] = at[d];
        g_pbias[L * 64 + s] = bi[d];
    }
}

// ------- single-pass decoupled-lookback scan; zeroes g_deg; reduces g_asum ---------
__global__ void scan_kernel() {
    __shared__ int wsum[32];
    __shared__ int s_run;
    __shared__ float fsum[32];
    int b = blockIdx.x, tid = threadIdx.x, lane = tid & 31, wid = tid >> 5;
    int i = b * 1024 + tid;
    int v = (i < Nn) ? g_deg[i] : 0;
    if (i < Nn) g_deg[i] = 0;            // ready for next call's count
    if (b == 0) {
        float a = g_asum[tid];           // COUNT_BLOCKS == 1024 == blockDim
        #pragma unroll
        for (int o = 16; o; o >>= 1) a += __shfl_xor_sync(FULLMASK, a, o);
        if (lane == 0) fsum[wid] = a;
    }
    int x = v;
    #pragma unroll
    for (int o = 1; o < 32; o <<= 1) {
        int y = __shfl_up_sync(FULLMASK, x, o);
        if (lane >= o) x += y;
    }
    if (lane == 31) wsum[wid] = x;
    __syncthreads();
    if (wid == 0) {
        int w = wsum[lane];
        #pragma unroll
        for (int o = 1; o < 32; o <<= 1) {
            int y = __shfl_up_sync(FULLMASK, w, o);
            if (lane >= o) w += y;
        }
        wsum[lane] = w;
        if (b == 0) {
            float a = fsum[lane];
            #pragma unroll
            for (int o = 16; o; o >>= 1) a += __shfl_xor_sync(FULLMASK, a, o);
            if (lane == 0) g_attrsum = a;
        }
    }
    __syncthreads();
    int excl  = (wid ? wsum[wid - 1] : 0) + x - v;
    int total = wsum[31];
    if (tid == 0) {
        if (b == 0) {
            g_pref[0] = total; __threadfence(); g_flag[0] = 2;
            s_run = 0;
        } else {
            g_aggr[b] = total; __threadfence(); g_flag[b] = 1;
            int run = 0, idx = b - 1;
            while (true) {
                int f;
                do { f = g_flag[idx]; } while (f == 0);
                if (f == 2) { run += g_pref[idx]; break; }
                run += g_aggr[idx]; --idx;
            }
            g_pref[b] = run + total; __threadfence(); g_flag[b] = 2;
            s_run = run;
        }
    }
    __syncthreads();
    if (i < Nn) {
        int val = excl + s_run;
        g_indptr[i] = val;
        g_wpos[i]   = val;
    }
}

// ---------------- scatter edges into CSR-by-dst (solo: low regs, high residency) ----
__global__ void scatter_kernel(const int* __restrict__ src, const int* __restrict__ dst,
                               const float* __restrict__ attr) {
    int e = blockIdx.x * blockDim.x + threadIdx.x;
    if (e >= Ee) return;
    int d = dst[e];
    int p = atomicAdd(&g_wpos[d], 1);
    g_csr[p] = make_int2(src[e], __float_as_int(attr[e]));
}

// ---------------- dual GEMM body (R12 version: float2 weight loads + pack2) ---------
template <int K, bool USE_GH>
__device__ __forceinline__ void gemm_body(const float* __restrict__ X,
                                          const float* __restrict__ pWl,
                                          const float* __restrict__ pWr,
                                          const float* __restrict__ bl,
                                          const float* __restrict__ br,
                                          int bid, int tid) {
    int warp = tid >> 5, lane = tid & 31;
    int row0 = bid * 64 + warp * 8;
    const float* __restrict__ IN = USE_GH ? g_h : X;
    const float2* __restrict__ wl2p = (const float2*)pWl;
    const float2* __restrict__ wr2p = (const float2*)pWr;
    unsigned long long aL[8], aR[8];
    #pragma unroll
    for (int j = 0; j < 8; j++) { aL[j] = 0ull; aR[j] = 0ull; }
    #pragma unroll 2
    for (int k0 = 0; k0 < K; k0 += 4) {
        unsigned long long wl[4], wr[4];
        #pragma unroll
        for (int u = 0; u < 4; u++) {
            float2 a = wl2p[(k0 + u) * 32 + lane]; wl[u] = pack2(a.x, a.y);
            float2 b = wr2p[(k0 + u) * 32 + lane]; wr[u] = pack2(b.x, b.y);
        }
        #pragma unroll
        for (int j = 0; j < 8; j++) {
            int gr = row0 + j;
            float4 xv = (gr < Nn) ? *(const float4*)&IN[gr * K + k0]
                                  : make_float4(0.f, 0.f, 0.f, 0.f);
            unsigned long long x0 = pack2(xv.x, xv.x), x1 = pack2(xv.y, xv.y);
            unsigned long long x2 = pack2(xv.z, xv.z), x3 = pack2(xv.w, xv.w);
            fma2(aL[j], x0, wl[0]); fma2(aR[j], x0, wr[0]);
            fma2(aL[j], x1, wl[1]); fma2(aR[j], x1, wr[1]);
            fma2(aL[j], x2, wl[2]); fma2(aR[j], x2, wr[2]);
            fma2(aL[j], x3, wl[3]); fma2(aR[j], x3, wr[3]);
        }
    }
    float b0 = bl[lane], b1 = bl[lane + 32];
    float c0 = br[lane], c1 = br[lane + 32];
    #pragma unroll
    for (int j = 0; j < 8; j++) {
        int gr = row0 + j;
        if (gr < Nn) {
            float2 l = unpack2(aL[j]); l.x += b0; l.y += b1;
            float2 r = unpack2(aR[j]); r.x += c0; r.y += c1;
            *(float2*)&g_xl[gr * 64 + 2 * lane] = l;
            *(float2*)&g_xr[gr * 64 + 2 * lane] = r;
        }
    }
}

__global__ void gemm1_kernel(const float* __restrict__ X,
                             const float* __restrict__ bl1, const float* __restrict__ br1) {
    gemm_body<Din, false>(X, g_pwl1, g_pwr1, bl1, br1, blockIdx.x, threadIdx.x);
}

__global__ void gemm2_kernel(const float* __restrict__ bl2, const float* __restrict__ br2) {
    gemm_body<Dh, true>(nullptr, g_pwl2, g_pwr2, bl2, br2, blockIdx.x, threadIdx.x);
}

// ---------------- GATv2: 8 lanes/node, 4 nodes/warp, contiguous-line lane map -------
// lane k (in group) owns slots [4k,4k+4) and [32+4k,32+4k+4): each LDG.128 covers
// ONE 128B line per group (4 wavefronts/instr instead of 8, no line double-touch).
// Fixed-reference softmax (anchor = self-loop logit), branchless invalid edges.
__global__ void __launch_bounds__(256) gat_kernel(int layer) {
    int warp = (blockIdx.x * blockDim.x + threadIdx.x) >> 5;
    int lane = threadIdx.x & 31;
    int grp = lane >> 3, seg = lane & 7;
    int node = warp * 4 + grp;
    bool nvalid = node < Nn;
    if (!nvalid) node = Nn - 1;
    int off0 = seg * 4;            // slots [4k, 4k+4)
    int off1 = 32 + seg * 4;       // slots [32+4k, 32+4k+4)

    unsigned long long xr2[4], we2[4], a2[4];
    float at[8];
    {
        float4 v0 = *(const float4*)&g_xr[node * 64 + off0];
        float4 v1 = *(const float4*)&g_xr[node * 64 + off1];
        xr2[0] = pack2(v0.x, v0.y); xr2[1] = pack2(v0.z, v0.w);
        xr2[2] = pack2(v1.x, v1.y); xr2[3] = pack2(v1.z, v1.w);
        float4 w0 = *(const float4*)&g_pwe[layer * 64 + off0];
        float4 w1 = *(const float4*)&g_pwe[layer * 64 + off1];
        we2[0] = pack2(w0.x, w0.y); we2[1] = pack2(w0.z, w0.w);
        we2[2] = pack2(w1.x, w1.y); we2[3] = pack2(w1.z, w1.w);
        float4 t0 = *(const float4*)&g_patt[layer * 64 + off0];
        float4 t1 = *(const float4*)&g_patt[layer * 64 + off1];
        at[0]=t0.x; at[1]=t0.y; at[2]=t0.z; at[3]=t0.w;
        at[4]=t1.x; at[5]=t1.y; at[6]=t1.z; at[7]=t1.w;
    }
    float mean_attr = g_attrsum * (1.0f / Ee);
    int beg = g_indptr[node];
    int deg = g_indptr[node + 1] - beg;

    // ---- self loop first: anchor logit m, a = xl_self, s = 1 ----
    float m, s = 1.f;
    {
        float4 v0 = *(const float4*)&g_xl[node * 64 + off0];
        float4 v1 = *(const float4*)&g_xl[node * 64 + off1];
        a2[0] = pack2(v0.x, v0.y); a2[1] = pack2(v0.z, v0.w);
        a2[2] = pack2(v1.x, v1.y); a2[3] = pack2(v1.z, v1.w);
        unsigned long long ma2 = pack2(mean_attr, mean_attr);
        float p = 0.f;
        #pragma unroll
        for (int i = 0; i < 4; i++) {
            unsigned long long t = fma2v(ma2, we2[i], add2(a2[i], xr2[i]));
            float2 u = unpack2(t);
            float l0 = fmaxf(u.x, 0.2f * u.x);
            float l1 = fmaxf(u.y, 0.2f * u.y);
            p = fmaf(l0, at[2 * i], p);
            p = fmaf(l1, at[2 * i + 1], p);
        }
        p += __shfl_xor_sync(FULLMASK, p, 1);
        p += __shfl_xor_sync(FULLMASK, p, 2);
        p += __shfl_xor_sync(FULLMASK, p, 4);
        m = p;
    }

    int tmax = deg;
    tmax = max(tmax, __shfl_xor_sync(FULLMASK, tmax, 8));
    tmax = max(tmax, __shfl_xor_sync(FULLMASK, tmax, 16));

    if (tmax > 0) {
        int2 eA = g_csr[min(beg,     Ee - 1)];
        int2 eB = g_csr[min(beg + 1, Ee - 1)];
        int2 eC = g_csr[min(beg + 2, Ee - 1)];
        unsigned long long xA[4], xB[4];
        {
            float4 v0 = *(const float4*)&g_xl[eA.x * 64 + off0];
            float4 v1 = *(const float4*)&g_xl[eA.x * 64 + off1];
            xA[0] = pack2(v0.x, v0.y); xA[1] = pack2(v0.z, v0.w);
            xA[2] = pack2(v1.x, v1.y); xA[3] = pack2(v1.z, v1.w);
        }
        int t2 = (tmax + 1) & ~1;          // even trip count, pairs (j, j+1)
        for (int j = 0; j < t2; j += 2) {
            {
                float4 v0 = *(const float4*)&g_xl[eB.x * 64 + off0];
                float4 v1 = *(const float4*)&g_xl[eB.x * 64 + off1];
                xB[0] = pack2(v0.x, v0.y); xB[1] = pack2(v0.z, v0.w);
                xB[2] = pack2(v1.x, v1.y); xB[3] = pack2(v1.z, v1.w);
            }
            int2 eD = g_csr[min(beg + j + 3, Ee - 1)];

            {
                float attr = __int_as_float(eA.y);
                unsigned long long at2v = pack2(attr, attr);
                float p = 0.f;
                #pragma unroll
                for (int i = 0; i < 4; i++) {
                    unsigned long long t = fma2v(at2v, we2[i], add2(xA[i], xr2[i]));
                    float2 u = unpack2(t);
                    float l0 = fmaxf(u.x, 0.2f * u.x);
                    float l1 = fmaxf(u.y, 0.2f * u.y);
                    p = fmaf(l0, at[2 * i], p);
                    p = fmaf(l1, at[2 * i + 1], p);
                }
                p += __shfl_xor_sync(FULLMASK, p, 1);
                p += __shfl_xor_sync(FULLMASK, p, 2);
                p += __shfl_xor_sync(FULLMASK, p, 4);
                if (j >= deg) p = -3.0e38f;
                float z = __expf(p - m);
                s += z;
                unsigned long long z2 = pack2(z, z);
                #pragma unroll
                for (int i = 0; i < 4; i++) a2[i] = fma2v(xA[i], z2, a2[i]);
            }

            {
                float4 v0 = *(const float4*)&g_xl[eC.x * 64 + off0];
                float4 v1 = *(const float4*)&g_xl[eC.x * 64 + off1];
                xA[0] = pack2(v0.x, v0.y); xA[1] = pack2(v0.z, v0.w);
                xA[2] = pack2(v1.x, v1.y); xA[3] = pack2(v1.z, v1.w);
            }
            int2 eE = g_csr[min(beg + j + 4, Ee - 1)];

            {
                float attr = __int_as_float(eB.y);
                unsigned long long at2v = pack2(attr, attr);
                float p = 0.f;
                #pragma unroll
                for (int i = 0; i < 4; i++) {
                    unsigned long long t = fma2v(at2v, we2[i], add2(xB[i], xr2[i]));
                    float2 u = unpack2(t);
                    float l0 = fmaxf(u.x, 0.2f * u.x);
                    float l1 = fmaxf(u.y, 0.2f * u.y);
                    p = fmaf(l0, at[2 * i], p);
                    p = fmaf(l1, at[2 * i + 1], p);
                }
                p += __shfl_xor_sync(FULLMASK, p, 1);
                p += __shfl_xor_sync(FULLMASK, p, 2);
                p += __shfl_xor_sync(FULLMASK, p, 4);
                if (j + 1 >= deg) p = -3.0e38f;
                float z = __expf(p - m);
                s += z;
                unsigned long long z2 = pack2(z, z);
                #pragma unroll
                for (int i = 0; i < 4; i++) a2[i] = fma2v(xB[i], z2, a2[i]);
            }

            eA = eC; eB = eD; eC = eE;
        }
    }

    float inv = 1.f / (s + 1e-16f);
    if (nvalid) {
        float o[8];
        #pragma unroll
        for (int i = 0; i < 4; i++) {
            float2 u = unpack2(a2[i]);
            int slot = (i < 2) ? (off0 + 2 * i) : (off1 + 2 * (i - 2));
            float v0 = fmaf(u.x, inv, g_pbias[layer * 64 + slot]);
            float v1 = fmaf(u.y, inv, g_pbias[layer * 64 + slot + 1]);
            o[2 * i]     = v0 > 0.f ? v0 : expm1f(v0);   // ELU
            o[2 * i + 1] = v1 > 0.f ? v1 : expm1f(v1);
        }
        *(float4*)&g_h[node * 64 + off0] = make_float4(o[0], o[1], o[2], o[3]);
        *(float4*)&g_h[node * 64 + off1] = make_float4(o[4], o[5], o[6], o[7]);
    }
}

// ---------------- mean pool per graph (batch sorted; storage-order dims) -----------
__global__ void pool_kernel(const int* __restrict__ batch) {
    int d = threadIdx.x;                 // 64 threads = 64 storage slots
    int n0 = blockIdx.x * 256;
    int n1 = n0 + 256; if (n1 > Nn) n1 = Nn;
    float acc = 0.f; int curg = -1; int c = 0;
    for (int n = n0; n < n1; ++n) {
        int g = batch[n];
        if (g != curg) {
            if (curg >= 0) {
                atomicAdd(&g_pooled[curg * Dh + d], acc);
                if (d == 0) atomicAdd(&g_cnt[curg], c);
            }
            curg = g; acc = 0.f; c = 0;
        }
        acc += g_h[n * Dh + d];
        ++c;
    }
    if (curg >= 0) {
        atomicAdd(&g_pooled[curg * Dh + d], acc);
        if (d == 0) atomicAdd(&g_cnt[curg], c);
    }
}

// ---------------- classifier (un-permutes storage -> dim) ----------------
__global__ void cls_kernel(const float* __restrict__ Wc, const float* __restrict__ bc,
                           float* __restrict__ out) {
    int t = threadIdx.x;                 // 640 threads
    int g = t / NCLS, c = t - g * NCLS;
    float invc = 1.f / fmaxf((float)g_cnt[g], 1.f);
    float acc = bc[c];
    #pragma unroll 8
    for (int s = 0; s < Dh; ++s) {
        int d = (s >> 1) + ((s & 1) << 5);     // storage slot -> true dim
        acc += g_pooled[g * Dh + s] * invc * Wc[d * NCLS + c];
    }
    out[t] = acc;
}

// ---------------- launch: forked-graph two-branch pipeline ----------------
extern "C" void kernel_launch(void* const* d_in, const int* in_sizes, int n_in,
                              void* d_out, int out_size) {
    const float* x    = (const float*)d_in[0];
    const int*   ei   = (const int*)  d_in[1];
    const float* eatt = (const float*)d_in[2];
    const int*   batch= (const int*)  d_in[3];
    const float* Wl1 = (const float*)d_in[4],  *bl1 = (const float*)d_in[5];
    const float* Wr1 = (const float*)d_in[6],  *br1 = (const float*)d_in[7];
    const float* We1 = (const float*)d_in[8],  *att1= (const float*)d_in[9];
    const float* b1  = (const float*)d_in[10];
    const float* Wl2 = (const float*)d_in[11], *bl2 = (const float*)d_in[12];
    const float* Wr2 = (const float*)d_in[13], *br2 = (const float*)d_in[14];
    const float* We2 = (const float*)d_in[15], *att2= (const float*)d_in[16];
    const float* b2  = (const float*)d_in[17];
    const float* Wc  = (const float*)d_in[18], *bc  = (const float*)d_in[19];
    float* out = (float*)d_out;

    const int* src = ei;
    const int* dst = ei + Ee;

    int gat_blocks = (Nn / 4 + 7) / 8 + 1;   // warps of 4 nodes, 8 warps/block

    // fork resources (created per call; NOT destroyed — a forked stream must
    // outlive the capture. kernel_launch runs only twice, so this leaks 2
    // streams + 4 events total: host-side, no device memory.)
    cudaStream_t s2;
    cudaStreamCreateWithFlags(&s2, cudaStreamNonBlocking);
    cudaEvent_t eFork, eJoin;
    cudaEventCreateWithFlags(&eFork, cudaEventDisableTiming);
    cudaEventCreateWithFlags(&eJoin, cudaEventDisableTiming);

    // fork: side branch roots at capture start
    cudaEventRecord(eFork, 0);
    cudaStreamWaitEvent(s2, eFork, 0);

    // branch B (side stream): weight permute -> gemm1 (writes g_xl/g_xr)
    initB_kernel<<<49, 256, 0, s2>>>(Wl1, Wr1, Wl2, Wr2, We1, att1, b1, We2, att2, b2);
    gemm1_kernel<<<GEMM1_BLOCKS, 256, 0, s2>>>(x, bl1, br1);
    cudaEventRecord(eJoin, s2);

    // branch A (main stream): zero+count -> scan -> scatter (writes g_csr)
    initA_kernel<<<196 + COUNT_BLOCKS, 256>>>(dst, eatt);
    scan_kernel<<<NBLK, 1024>>>();
    scatter_kernel<<<SCAT_BLOCKS, 256>>>(src, dst, eatt);

    // join: gat needs both g_csr (A) and g_xl/g_xr (B)
    cudaStreamWaitEvent(0, eJoin, 0);

    gat_kernel<<<gat_blocks, 256>>>(0);
    gemm2_kernel<<<GEMM1_BLOCKS, 256>>>(bl2, br2);
    gat_kernel<<<gat_blocks, 256>>>(1);
    pool_kernel<<<(Nn + 255) / 256, 64>>>(batch);
    cls_kernel<<<1, Gg * NCLS>>>(Wc, bc, out);
}

// round 16
// speedup vs baseline: 1.0076x; 1.0076x over previous
#include <cuda_runtime.h>
#include <math.h>

#define Nn   50000
#define Ee   1600000
#define Dh   64
#define Din  128
#define Gg   64
#define NCLS 10
#define NBLK 49              // ceil(Nn/1024)
#define GEMM_BLOCKS 782      // ceil(Nn/64), 64 rows/block
#define SCAT_BLOCKS  6250    // ceil(Ee/256)
#define COUNT_BLOCKS 1024
#define FULLMASK 0xffffffffu

// ---------------- scratch (device globals; referenced ONLY in device code) ----------
__device__ float g_xl[Nn * Dh];      // pair-interleaved: slot 2l,2l+1 = dims l, l+32
__device__ float g_xr[Nn * Dh];
__device__ float g_h [Nn * Dh];
__device__ int   g_deg[Nn];          // zero at entry; scan re-zeroes after reading
__device__ int   g_indptr[Nn + 1];
__device__ int   g_wpos[Nn];
__device__ int2  g_csr[Ee];          // {src, attr-as-int}
__device__ float g_asum[COUNT_BLOCKS];
__device__ float g_attrsum;
__device__ float g_pooled[Gg * Dh];
__device__ int   g_cnt[Gg];
__device__ volatile int g_flag[NBLK];
__device__ volatile int g_aggr[NBLK];
__device__ volatile int g_pref[NBLK];
// pre-permuted weights (pair-interleaved columns; layer-2 rows in storage order)
__device__ float g_pwl1[Din * Dh], g_pwr1[Din * Dh];
__device__ float g_pwl2[Dh * Dh],  g_pwr2[Dh * Dh];
__device__ float g_pwe[2 * 64], g_patt[2 * 64], g_pbias[2 * 64];

// ---------------- f32x2 helpers ----------------
__device__ __forceinline__ unsigned long long pack2(float x, float y) {
    unsigned long long r;
    asm("mov.b64 %0, {%1, %2};" : "=l"(r) : "f"(x), "f"(y));
    return r;
}
__device__ __forceinline__ void fma2(unsigned long long& d, unsigned long long a,
                                     unsigned long long b) {
    asm("fma.rn.f32x2 %0, %1, %2, %3;" : "=l"(d) : "l"(a), "l"(b), "l"(d));
}
__device__ __forceinline__ unsigned long long fma2v(unsigned long long a,
                                                    unsigned long long b,
                                                    unsigned long long c) {
    unsigned long long r;
    asm("fma.rn.f32x2 %0, %1, %2, %3;" : "=l"(r) : "l"(a), "l"(b), "l"(c));
    return r;
}
__device__ __forceinline__ unsigned long long add2(unsigned long long a,
                                                   unsigned long long b) {
    unsigned long long r;
    asm("add.rn.f32x2 %0, %1, %2;" : "=l"(r) : "l"(a), "l"(b));
    return r;
}
__device__ __forceinline__ float2 unpack2(unsigned long long v) {
    float2 r;
    asm("mov.b64 {%0, %1}, %2;" : "=f"(r.x), "=f"(r.y) : "l"(v));
    return r;
}

// ------- initA: zero CSR-side scratch + degree count (branch A root) ---------------
__global__ void initA_kernel(const int* __restrict__ dst, const float* __restrict__ attr) {
    int b = blockIdx.x, t = threadIdx.x;
    if (b < 196) {
        int i = b * 256 + t;
        if (i < Gg * Dh) g_pooled[i] = 0.f;
        if (i < Gg) g_cnt[i] = 0;
        if (i < NBLK) g_flag[i] = 0;
        if (i == 0) g_indptr[Nn] = Ee;
        return;
    }
    // count part: grid-strided over edges; partial attr sums into g_asum
    int cb = b - 196;
    float v = 0.f;
    for (int e = cb * 256 + t; e < Ee; e += COUNT_BLOCKS * 256) {
        atomicAdd(&g_deg[dst[e]], 1);
        v += attr[e];
    }
    #pragma unroll
    for (int o = 16; o; o >>= 1) v += __shfl_xor_sync(FULLMASK, v, o);
    __shared__ float red[8];
    int lane = t & 31, wid = t >> 5;
    if (lane == 0) red[wid] = v;
    __syncthreads();
    if (t < 8) {
        float w = red[t];
        #pragma unroll
        for (int o = 4; o; o >>= 1) w += __shfl_xor_sync(0xffu, w, o);
        if (t == 0) g_asum[cb] = w;
    }
}

// ------- initB: weight / vector permutation (branch B root) ------------------------
__global__ void initB_kernel(const float* __restrict__ Wl1, const float* __restrict__ Wr1,
                             const float* __restrict__ Wl2, const float* __restrict__ Wr2,
                             const float* __restrict__ We1, const float* __restrict__ att1,
                             const float* __restrict__ b1,
                             const float* __restrict__ We2, const float* __restrict__ att2,
                             const float* __restrict__ b2) {
    int b = blockIdx.x, t = threadIdx.x;
    if (b < 48) {
        int idx = b * 256 + t;                        // 48*256 = 12288 = Din*Dh + Dh*Dh
        if (idx < Din * Dh) {                         // layer-1 weights [128][64]
            int k = idx >> 6, d = idx & 63;
            int st = 2 * (d & 31) + (d >> 5);
            g_pwl1[k * 64 + st] = Wl1[idx];
            g_pwr1[k * 64 + st] = Wr1[idx];
        } else {                                      // layer-2 weights [64][64]
            int j = idx - Din * Dh;
            int k = j >> 6, d = j & 63;
            int srow = 2 * (k & 31) + (k >> 5);       // input rows in storage order
            int st   = 2 * (d & 31) + (d >> 5);
            g_pwl2[srow * 64 + st] = Wl2[j];
            g_pwr2[srow * 64 + st] = Wr2[j];
        }
        return;
    }
    if (t < 128) {
        int L = t >> 6, s = t & 63;
        int d = (s >> 1) + ((s & 1) << 5);            // storage slot -> true dim
        const float* We = L ? We2 : We1;
        const float* at = L ? att2 : att1;
        const float* bi = L ? b2  : b1;
        g_pwe  [L * 64 + s] = We[d];
        g_patt [L * 64 + s] = at[d];
        g_pbias[L * 64 + s] = bi[d];
    }
}

// ------- single-pass decoupled-lookback scan; zeroes g_deg; reduces g_asum ---------
__global__ void scan_kernel() {
    __shared__ int wsum[32];
    __shared__ int s_run;
    __shared__ float fsum[32];
    int b = blockIdx.x, tid = threadIdx.x, lane = tid & 31, wid = tid >> 5;
    int i = b * 1024 + tid;
    int v = (i < Nn) ? g_deg[i] : 0;
    if (i < Nn) g_deg[i] = 0;            // ready for next call's count
    if (b == 0) {
        float a = g_asum[tid];           // COUNT_BLOCKS == 1024 == blockDim
        #pragma unroll
        for (int o = 16; o; o >>= 1) a += __shfl_xor_sync(FULLMASK, a, o);
        if (lane == 0) fsum[wid] = a;
    }
    int x = v;
    #pragma unroll
    for (int o = 1; o < 32; o <<= 1) {
        int y = __shfl_up_sync(FULLMASK, x, o);
        if (lane >= o) x += y;
    }
    if (lane == 31) wsum[wid] = x;
    __syncthreads();
    if (wid == 0) {
        int w = wsum[lane];
        #pragma unroll
        for (int o = 1; o < 32; o <<= 1) {
            int y = __shfl_up_sync(FULLMASK, w, o);
            if (lane >= o) w += y;
        }
        wsum[lane] = w;
        if (b == 0) {
            float a = fsum[lane];
            #pragma unroll
            for (int o = 16; o; o >>= 1) a += __shfl_xor_sync(FULLMASK, a, o);
            if (lane == 0) g_attrsum = a;
        }
    }
    __syncthreads();
    int excl  = (wid ? wsum[wid - 1] : 0) + x - v;
    int total = wsum[31];
    if (tid == 0) {
        if (b == 0) {
            g_pref[0] = total; __threadfence(); g_flag[0] = 2;
            s_run = 0;
        } else {
            g_aggr[b] = total; __threadfence(); g_flag[b] = 1;
            int run = 0, idx = b - 1;
            while (true) {
                int f;
                do { f = g_flag[idx]; } while (f == 0);
                if (f == 2) { run += g_pref[idx]; break; }
                run += g_aggr[idx]; --idx;
            }
            g_pref[b] = run + total; __threadfence(); g_flag[b] = 2;
            s_run = run;
        }
    }
    __syncthreads();
    if (i < Nn) {
        int val = excl + s_run;
        g_indptr[i] = val;
        g_wpos[i]   = val;
    }
}

// ---------------- scatter edges into CSR-by-dst (solo: low regs, high residency) ----
__global__ void scatter_kernel(const int* __restrict__ src, const int* __restrict__ dst,
                               const float* __restrict__ attr) {
    int e = blockIdx.x * blockDim.x + threadIdx.x;
    if (e >= Ee) return;
    int d = dst[e];
    int p = atomicAdd(&g_wpos[d], 1);
    g_csr[p] = make_int2(src[e], __float_as_int(attr[e]));
}

// ---------------- dual GEMM body: 4 rows/thread, 512 thr/block (occupancy 2x) -------
template <int K, bool USE_GH>
__device__ __forceinline__ void gemm_body(const float* __restrict__ X,
                                          const float* __restrict__ pWl,
                                          const float* __restrict__ pWr,
                                          const float* __restrict__ bl,
                                          const float* __restrict__ br,
                                          int bid, int tid) {
    int warp = tid >> 5, lane = tid & 31;       // 16 warps, 4 rows each
    int row0 = bid * 64 + warp * 4;
    const float* __restrict__ IN = USE_GH ? g_h : X;
    const float2* __restrict__ wl2p = (const float2*)pWl;
    const float2* __restrict__ wr2p = (const float2*)pWr;
    unsigned long long aL[4], aR[4];
    #pragma unroll
    for (int j = 0; j < 4; j++) { aL[j] = 0ull; aR[j] = 0ull; }
    #pragma unroll 2
    for (int k0 = 0; k0 < K; k0 += 4) {
        unsigned long long wl[4], wr[4];
        #pragma unroll
        for (int u = 0; u < 4; u++) {
            float2 a = wl2p[(k0 + u) * 32 + lane]; wl[u] = pack2(a.x, a.y);
            float2 b = wr2p[(k0 + u) * 32 + lane]; wr[u] = pack2(b.x, b.y);
        }
        #pragma unroll
        for (int j = 0; j < 4; j++) {
            int gr = row0 + j;
            float4 xv = (gr < Nn) ? *(const float4*)&IN[gr * K + k0]
                                  : make_float4(0.f, 0.f, 0.f, 0.f);
            unsigned long long x0 = pack2(xv.x, xv.x), x1 = pack2(xv.y, xv.y);
            unsigned long long x2 = pack2(xv.z, xv.z), x3 = pack2(xv.w, xv.w);
            fma2(aL[j], x0, wl[0]); fma2(aR[j], x0, wr[0]);
            fma2(aL[j], x1, wl[1]); fma2(aR[j], x1, wr[1]);
            fma2(aL[j], x2, wl[2]); fma2(aR[j], x2, wr[2]);
            fma2(aL[j], x3, wl[3]); fma2(aR[j], x3, wr[3]);
        }
    }
    float b0 = bl[lane], b1 = bl[lane + 32];
    float c0 = br[lane], c1 = br[lane + 32];
    #pragma unroll
    for (int j = 0; j < 4; j++) {
        int gr = row0 + j;
        if (gr < Nn) {
            float2 l = unpack2(aL[j]); l.x += b0; l.y += b1;
            float2 r = unpack2(aR[j]); r.x += c0; r.y += c1;
            *(float2*)&g_xl[gr * 64 + 2 * lane] = l;
            *(float2*)&g_xr[gr * 64 + 2 * lane] = r;
        }
    }
}

__global__ void __launch_bounds__(512) gemm1_kernel(const float* __restrict__ X,
                             const float* __restrict__ bl1, const float* __restrict__ br1) {
    gemm_body<Din, false>(X, g_pwl1, g_pwr1, bl1, br1, blockIdx.x, threadIdx.x);
}

__global__ void __launch_bounds__(512) gemm2_kernel(const float* __restrict__ bl2,
                                                    const float* __restrict__ br2) {
    gemm_body<Dh, true>(nullptr, g_pwl2, g_pwr2, bl2, br2, blockIdx.x, threadIdx.x);
}

// ---------------- GATv2: 8 lanes/node, 4 nodes/warp, fixed-reference softmax --------
// (R14 best-known version, remap reverted)
__global__ void __launch_bounds__(256) gat_kernel(int layer) {
    int warp = (blockIdx.x * blockDim.x + threadIdx.x) >> 5;
    int lane = threadIdx.x & 31;
    int grp = lane >> 3, seg = lane & 7;
    int node = warp * 4 + grp;
    bool nvalid = node < Nn;
    if (!nvalid) node = Nn - 1;
    int base = node * 64 + seg * 8;

    unsigned long long xr2[4], we2[4], a2[4];
    float at[8];
    {
        float4 v0 = *(const float4*)&g_xr[base];
        float4 v1 = *(const float4*)&g_xr[base + 4];
        xr2[0] = pack2(v0.x, v0.y); xr2[1] = pack2(v0.z, v0.w);
        xr2[2] = pack2(v1.x, v1.y); xr2[3] = pack2(v1.z, v1.w);
        float4 w0 = *(const float4*)&g_pwe[layer * 64 + seg * 8];
        float4 w1 = *(const float4*)&g_pwe[layer * 64 + seg * 8 + 4];
        we2[0] = pack2(w0.x, w0.y); we2[1] = pack2(w0.z, w0.w);
        we2[2] = pack2(w1.x, w1.y); we2[3] = pack2(w1.z, w1.w);
        float4 t0 = *(const float4*)&g_patt[layer * 64 + seg * 8];
        float4 t1 = *(const float4*)&g_patt[layer * 64 + seg * 8 + 4];
        at[0]=t0.x; at[1]=t0.y; at[2]=t0.z; at[3]=t0.w;
        at[4]=t1.x; at[5]=t1.y; at[6]=t1.z; at[7]=t1.w;
    }
    float mean_attr = g_attrsum * (1.0f / Ee);
    int beg = g_indptr[node];
    int deg = g_indptr[node + 1] - beg;

    // ---- self loop first: anchor logit m, a = xl_self, s = 1 ----
    float m, s = 1.f;
    {
        float4 v0 = *(const float4*)&g_xl[base];
        float4 v1 = *(const float4*)&g_xl[base + 4];
        a2[0] = pack2(v0.x, v0.y); a2[1] = pack2(v0.z, v0.w);
        a2[2] = pack2(v1.x, v1.y); a2[3] = pack2(v1.z, v1.w);
        unsigned long long ma2 = pack2(mean_attr, mean_attr);
        float p = 0.f;
        #pragma unroll
        for (int i = 0; i < 4; i++) {
            unsigned long long t = fma2v(ma2, we2[i], add2(a2[i], xr2[i]));
            float2 u = unpack2(t);
            float l0 = fmaxf(u.x, 0.2f * u.x);
            float l1 = fmaxf(u.y, 0.2f * u.y);
            p = fmaf(l0, at[2 * i], p);
            p = fmaf(l1, at[2 * i + 1], p);
        }
        p += __shfl_xor_sync(FULLMASK, p, 1);
        p += __shfl_xor_sync(FULLMASK, p, 2);
        p += __shfl_xor_sync(FULLMASK, p, 4);
        m = p;
    }

    int tmax = deg;
    tmax = max(tmax, __shfl_xor_sync(FULLMASK, tmax, 8));
    tmax = max(tmax, __shfl_xor_sync(FULLMASK, tmax, 16));

    if (tmax > 0) {
        int2 eA = g_csr[min(beg,     Ee - 1)];
        int2 eB = g_csr[min(beg + 1, Ee - 1)];
        int2 eC = g_csr[min(beg + 2, Ee - 1)];
        unsigned long long xA[4], xB[4];
        {
            const float4* xp = (const float4*)&g_xl[eA.x * 64 + seg * 8];
            float4 v0 = xp[0], v1 = xp[1];
            xA[0] = pack2(v0.x, v0.y); xA[1] = pack2(v0.z, v0.w);
            xA[2] = pack2(v1.x, v1.y); xA[3] = pack2(v1.z, v1.w);
        }
        int t2 = (tmax + 1) & ~1;          // even trip count, pairs (j, j+1)
        for (int j = 0; j < t2; j += 2) {
            {
                const float4* xp = (const float4*)&g_xl[eB.x * 64 + seg * 8];
                float4 v0 = xp[0], v1 = xp[1];
                xB[0] = pack2(v0.x, v0.y); xB[1] = pack2(v0.z, v0.w);
                xB[2] = pack2(v1.x, v1.y); xB[3] = pack2(v1.z, v1.w);
            }
            int2 eD = g_csr[min(beg + j + 3, Ee - 1)];

            {
                float attr = __int_as_float(eA.y);
                unsigned long long at2v = pack2(attr, attr);
                float p = 0.f;
                #pragma unroll
                for (int i = 0; i < 4; i++) {
                    unsigned long long t = fma2v(at2v, we2[i], add2(xA[i], xr2[i]));
                    float2 u = unpack2(t);
                    float l0 = fmaxf(u.x, 0.2f * u.x);
                    float l1 = fmaxf(u.y, 0.2f * u.y);
                    p = fmaf(l0, at[2 * i], p);
                    p = fmaf(l1, at[2 * i + 1], p);
                }
                p += __shfl_xor_sync(FULLMASK, p, 1);
                p += __shfl_xor_sync(FULLMASK, p, 2);
                p += __shfl_xor_sync(FULLMASK, p, 4);
                if (j >= deg) p = -3.0e38f;
                float z = __expf(p - m);
                s += z;
                unsigned long long z2 = pack2(z, z);
                #pragma unroll
                for (int i = 0; i < 4; i++) a2[i] = fma2v(xA[i], z2, a2[i]);
            }

            {
                const float4* xp = (const float4*)&g_xl[eC.x * 64 + seg * 8];
                float4 v0 = xp[0], v1 = xp[1];
                xA[0] = pack2(v0.x, v0.y); xA[1] = pack2(v0.z, v0.w);
                xA[2] = pack2(v1.x, v1.y); xA[3] = pack2(v1.z, v1.w);
            }
            int2 eE = g_csr[min(beg + j + 4, Ee - 1)];

            {
                float attr = __int_as_float(eB.y);
                unsigned long long at2v = pack2(attr, attr);
                float p = 0.f;
                #pragma unroll
                for (int i = 0; i < 4; i++) {
                    unsigned long long t = fma2v(at2v, we2[i], add2(xB[i], xr2[i]));
                    float2 u = unpack2(t);
                    float l0 = fmaxf(u.x, 0.2f * u.x);
                    float l1 = fmaxf(u.y, 0.2f * u.y);
                    p = fmaf(l0, at[2 * i], p);
                    p = fmaf(l1, at[2 * i + 1], p);
                }
                p += __shfl_xor_sync(FULLMASK, p, 1);
                p += __shfl_xor_sync(FULLMASK, p, 2);
                p += __shfl_xor_sync(FULLMASK, p, 4);
                if (j + 1 >= deg) p = -3.0e38f;
                float z = __expf(p - m);
                s += z;
                unsigned long long z2 = pack2(z, z);
                #pragma unroll
                for (int i = 0; i < 4; i++) a2[i] = fma2v(xB[i], z2, a2[i]);
            }

            eA = eC; eB = eD; eC = eE;
        }
    }

    float inv = 1.f / (s + 1e-16f);
    if (nvalid) {
        float o[8];
        #pragma unroll
        for (int i = 0; i < 4; i++) {
            float2 u = unpack2(a2[i]);
            float v0 = fmaf(u.x, inv, g_pbias[layer * 64 + seg * 8 + 2 * i]);
            float v1 = fmaf(u.y, inv, g_pbias[layer * 64 + seg * 8 + 2 * i + 1]);
            o[2 * i]     = v0 > 0.f ? v0 : expm1f(v0);   // ELU
            o[2 * i + 1] = v1 > 0.f ? v1 : expm1f(v1);
        }
        float4* hp = (float4*)&g_h[base];
        hp[0] = make_float4(o[0], o[1], o[2], o[3]);
        hp[1] = make_float4(o[4], o[5], o[6], o[7]);
    }
}

// ---------------- mean pool per graph (batch sorted; storage-order dims) -----------
__global__ void pool_kernel(const int* __restrict__ batch) {
    int d = threadIdx.x;                 // 64 threads = 64 storage slots
    int n0 = blockIdx.x * 256;
    int n1 = n0 + 256; if (n1 > Nn) n1 = Nn;
    float acc = 0.f; int curg = -1; int c = 0;
    for (int n = n0; n < n1; ++n) {
        int g = batch[n];
        if (g != curg) {
            if (curg >= 0) {
                atomicAdd(&g_pooled[curg * Dh + d], acc);
                if (d == 0) atomicAdd(&g_cnt[curg], c);
            }
            curg = g; acc = 0.f; c = 0;
        }
        acc += g_h[n * Dh + d];
        ++c;
    }
    if (curg >= 0) {
        atomicAdd(&g_pooled[curg * Dh + d], acc);
        if (d == 0) atomicAdd(&g_cnt[curg], c);
    }
}

// ---------------- classifier (un-permutes storage -> dim) ----------------
__global__ void cls_kernel(const float* __restrict__ Wc, const float* __restrict__ bc,
                           float* __restrict__ out) {
    int t = threadIdx.x;                 // 640 threads
    int g = t / NCLS, c = t - g * NCLS;
    float invc = 1.f / fmaxf((float)g_cnt[g], 1.f);
    float acc = bc[c];
    #pragma unroll 8
    for (int s = 0; s < Dh; ++s) {
        int d = (s >> 1) + ((s & 1) << 5);     // storage slot -> true dim
        acc += g_pooled[g * Dh + s] * invc * Wc[d * NCLS + c];
    }
    out[t] = acc;
}

// ---------------- launch: forked-graph two-branch pipeline ----------------
extern "C" void kernel_launch(void* const* d_in, const int* in_sizes, int n_in,
                              void* d_out, int out_size) {
    const float* x    = (const float*)d_in[0];
    const int*   ei   = (const int*)  d_in[1];
    const float* eatt = (const float*)d_in[2];
    const int*   batch= (const int*)  d_in[3];
    const float* Wl1 = (const float*)d_in[4],  *bl1 = (const float*)d_in[5];
    const float* Wr1 = (const float*)d_in[6],  *br1 = (const float*)d_in[7];
    const float* We1 = (const float*)d_in[8],  *att1= (const float*)d_in[9];
    const float* b1  = (const float*)d_in[10];
    const float* Wl2 = (const float*)d_in[11], *bl2 = (const float*)d_in[12];
    const float* Wr2 = (const float*)d_in[13], *br2 = (const float*)d_in[14];
    const float* We2 = (const float*)d_in[15], *att2= (const float*)d_in[16];
    const float* b2  = (const float*)d_in[17];
    const float* Wc  = (const float*)d_in[18], *bc  = (const float*)d_in[19];
    float* out = (float*)d_out;

    const int* src = ei;
    const int* dst = ei + Ee;

    int gat_blocks = (Nn / 4 + 7) / 8 + 1;   // warps of 4 nodes, 8 warps/block

    // fork resources (created per call; NOT destroyed — a forked stream must
    // outlive the capture. kernel_launch runs only twice, so this leaks 2
    // streams + 4 events total: host-side, no device memory.)
    cudaStream_t s2;
    cudaStreamCreateWithFlags(&s2, cudaStreamNonBlocking);
    cudaEvent_t eFork, eJoin;
    cudaEventCreateWithFlags(&eFork, cudaEventDisableTiming);
    cudaEventCreateWithFlags(&eJoin, cudaEventDisableTiming);

    // fork: side branch roots at capture start
    cudaEventRecord(eFork, 0);
    cudaStreamWaitEvent(s2, eFork, 0);

    // branch B (side stream): weight permute -> gemm1 (writes g_xl/g_xr)
    initB_kernel<<<49, 256, 0, s2>>>(Wl1, Wr1, Wl2, Wr2, We1, att1, b1, We2, att2, b2);
    gemm1_kernel<<<GEMM_BLOCKS, 512, 0, s2>>>(x, bl1, br1);
    cudaEventRecord(eJoin, s2);

    // branch A (main stream): zero+count -> scan -> scatter (writes g_csr)
    initA_kernel<<<196 + COUNT_BLOCKS, 256>>>(dst, eatt);
    scan_kernel<<<NBLK, 1024>>>();
    scatter_kernel<<<SCAT_BLOCKS, 256>>>(src, dst, eatt);

    // join: gat needs both g_csr (A) and g_xl/g_xr (B)
    cudaStreamWaitEvent(0, eJoin, 0);

    gat_kernel<<<gat_blocks, 256>>>(0);
    gemm2_kernel<<<GEMM_BLOCKS, 512>>>(bl2, br2);
    gat_kernel<<<gat_blocks, 256>>>(1);
    pool_kernel<<<(Nn + 255) / 256, 64>>>(batch);
    cls_kernel<<<1, Gg * NCLS>>>(Wc, bc, out);
}

// round 17
// speedup vs baseline: 1.0327x; 1.0249x over previous
#include <cuda_runtime.h>
#include <cuda_fp16.h>
#include <math.h>

#define Nn   50000
#define Ee   1600000
#define Dh   64
#define Din  128
#define Gg   64
#define NCLS 10
#define NBLK 49              // ceil(Nn/1024)
#define GEMM1_BLOCKS 782     // ceil(Nn/64)
#define SCAT_BLOCKS  6250    // ceil(Ee/256)
#define COUNT_BLOCKS 1024
#define FULLMASK 0xffffffffu

// ---------------- scratch (device globals; referenced ONLY in device code) ----------
__device__ __half g_xlh[Nn * Dh];    // fp16 xl: ONLY randomly-gathered tensor (halved bytes)
__device__ float g_xr[Nn * Dh];      // pair-interleaved: slot 2l,2l+1 = dims l, l+32
__device__ float g_h [Nn * Dh];
__device__ int   g_deg[Nn];          // zero at entry; scan re-zeroes after reading
__device__ int   g_indptr[Nn + 1];
__device__ int   g_wpos[Nn];
__device__ int2  g_csr[Ee];          // {src, attr-as-int}
__device__ float g_asum[COUNT_BLOCKS];
__device__ float g_attrsum;
__device__ float g_pooled[Gg * Dh];
__device__ int   g_cnt[Gg];
__device__ volatile int g_flag[NBLK];
__device__ volatile int g_aggr[NBLK];
__device__ volatile int g_pref[NBLK];
// pre-permuted weights (pair-interleaved columns; layer-2 rows in storage order)
__device__ float g_pwl1[Din * Dh], g_pwr1[Din * Dh];
__device__ float g_pwl2[Dh * Dh],  g_pwr2[Dh * Dh];
__device__ float g_pwe[2 * 64], g_patt[2 * 64], g_pbias[2 * 64];

// ---------------- f32x2 helpers ----------------
__device__ __forceinline__ unsigned long long pack2(float x, float y) {
    unsigned long long r;
    asm("mov.b64 %0, {%1, %2};" : "=l"(r) : "f"(x), "f"(y));
    return r;
}
__device__ __forceinline__ void fma2(unsigned long long& d, unsigned long long a,
                                     unsigned long long b) {
    asm("fma.rn.f32x2 %0, %1, %2, %3;" : "=l"(d) : "l"(a), "l"(b), "l"(d));
}
__device__ __forceinline__ unsigned long long fma2v(unsigned long long a,
                                                    unsigned long long b,
                                                    unsigned long long c) {
    unsigned long long r;
    asm("fma.rn.f32x2 %0, %1, %2, %3;" : "=l"(r) : "l"(a), "l"(b), "l"(c));
    return r;
}
__device__ __forceinline__ unsigned long long add2(unsigned long long a,
                                                   unsigned long long b) {
    unsigned long long r;
    asm("add.rn.f32x2 %0, %1, %2;" : "=l"(r) : "l"(a), "l"(b));
    return r;
}
__device__ __forceinline__ float2 unpack2(unsigned long long v) {
    float2 r;
    asm("mov.b64 {%0, %1}, %2;" : "=f"(r.x), "=f"(r.y) : "l"(v));
    return r;
}
// half2 (as u32) -> packed f32x2 pair
__device__ __forceinline__ unsigned long long h2_to_f2(unsigned int h) {
    float2 f = __half22float2(*(__half2*)&h);
    return pack2(f.x, f.y);
}

// ------- initA: zero CSR-side scratch + degree count (branch A root) ---------------
__global__ void initA_kernel(const int* __restrict__ dst, const float* __restrict__ attr) {
    int b = blockIdx.x, t = threadIdx.x;
    if (b < 196) {
        int i = b * 256 + t;
        if (i < Gg * Dh) g_pooled[i] = 0.f;
        if (i < Gg) g_cnt[i] = 0;
        if (i < NBLK) g_flag[i] = 0;
        if (i == 0) g_indptr[Nn] = Ee;
        return;
    }
    // count part: grid-strided over edges; partial attr sums into g_asum
    int cb = b - 196;
    float v = 0.f;
    for (int e = cb * 256 + t; e < Ee; e += COUNT_BLOCKS * 256) {
        atomicAdd(&g_deg[dst[e]], 1);
        v += attr[e];
    }
    #pragma unroll
    for (int o = 16; o; o >>= 1) v += __shfl_xor_sync(FULLMASK, v, o);
    __shared__ float red[8];
    int lane = t & 31, wid = t >> 5;
    if (lane == 0) red[wid] = v;
    __syncthreads();
    if (t < 8) {
        float w = red[t];
        #pragma unroll
        for (int o = 4; o; o >>= 1) w += __shfl_xor_sync(0xffu, w, o);
        if (t == 0) g_asum[cb] = w;
    }
}

// ------- initB: weight / vector permutation (branch B root) ------------------------
__global__ void initB_kernel(const float* __restrict__ Wl1, const float* __restrict__ Wr1,
                             const float* __restrict__ Wl2, const float* __restrict__ Wr2,
                             const float* __restrict__ We1, const float* __restrict__ att1,
                             const float* __restrict__ b1,
                             const float* __restrict__ We2, const float* __restrict__ att2,
                             const float* __restrict__ b2) {
    int b = blockIdx.x, t = threadIdx.x;
    if (b < 48) {
        int idx = b * 256 + t;                        // 48*256 = 12288 = Din*Dh + Dh*Dh
        if (idx < Din * Dh) {                         // layer-1 weights [128][64]
            int k = idx >> 6, d = idx & 63;
            int st = 2 * (d & 31) + (d >> 5);
            g_pwl1[k * 64 + st] = Wl1[idx];
            g_pwr1[k * 64 + st] = Wr1[idx];
        } else {                                      // layer-2 weights [64][64]
            int j = idx - Din * Dh;
            int k = j >> 6, d = j & 63;
            int srow = 2 * (k & 31) + (k >> 5);       // input rows in storage order
            int st   = 2 * (d & 31) + (d >> 5);
            g_pwl2[srow * 64 + st] = Wl2[j];
            g_pwr2[srow * 64 + st] = Wr2[j];
        }
        return;
    }
    if (t < 128) {
        int L = t >> 6, s = t & 63;
        int d = (s >> 1) + ((s & 1) << 5);            // storage slot -> true dim
        const float* We = L ? We2 : We1;
        const float* at = L ? att2 : att1;
        const float* bi = L ? b2  : b1;
        g_pwe  [L * 64 + s] = We[d];
        g_patt [L * 64 + s] = at[d];
        g_pbias[L * 64 + s] = bi[d];
    }
}

// ------- single-pass decoupled-lookback scan; zeroes g_deg; reduces g_asum ---------
__global__ void scan_kernel() {
    __shared__ int wsum[32];
    __shared__ int s_run;
    __shared__ float fsum[32];
    int b = blockIdx.x, tid = threadIdx.x, lane = tid & 31, wid = tid >> 5;
    int i = b * 1024 + tid;
    int v = (i < Nn) ? g_deg[i] : 0;
    if (i < Nn) g_deg[i] = 0;            // ready for next call's count
    if (b == 0) {
        float a = g_asum[tid];           // COUNT_BLOCKS == 1024 == blockDim
        #pragma unroll
        for (int o = 16; o; o >>= 1) a += __shfl_xor_sync(FULLMASK, a, o);
        if (lane == 0) fsum[wid] = a;
    }
    int x = v;
    #pragma unroll
    for (int o = 1; o < 32; o <<= 1) {
        int y = __shfl_up_sync(FULLMASK, x, o);
        if (lane >= o) x += y;
    }
    if (lane == 31) wsum[wid] = x;
    __syncthreads();
    if (wid == 0) {
        int w = wsum[lane];
        #pragma unroll
        for (int o = 1; o < 32; o <<= 1) {
            int y = __shfl_up_sync(FULLMASK, w, o);
            if (lane >= o) w += y;
        }
        wsum[lane] = w;
        if (b == 0) {
            float a = fsum[lane];
            #pragma unroll
            for (int o = 16; o; o >>= 1) a += __shfl_xor_sync(FULLMASK, a, o);
            if (lane == 0) g_attrsum = a;
        }
    }
    __syncthreads();
    int excl  = (wid ? wsum[wid - 1] : 0) + x - v;
    int total = wsum[31];
    if (tid == 0) {
        if (b == 0) {
            g_pref[0] = total; __threadfence(); g_flag[0] = 2;
            s_run = 0;
        } else {
            g_aggr[b] = total; __threadfence(); g_flag[b] = 1;
            int run = 0, idx = b - 1;
            while (true) {
                int f;
                do { f = g_flag[idx]; } while (f == 0);
                if (f == 2) { run += g_pref[idx]; break; }
                run += g_aggr[idx]; --idx;
            }
            g_pref[b] = run + total; __threadfence(); g_flag[b] = 2;
            s_run = run;
        }
    }
    __syncthreads();
    if (i < Nn) {
        int val = excl + s_run;
        g_indptr[i] = val;
        g_wpos[i]   = val;
    }
}

// ---------------- scatter edges into CSR-by-dst (solo: low regs, high residency) ----
__global__ void scatter_kernel(const int* __restrict__ src, const int* __restrict__ dst,
                               const float* __restrict__ attr) {
    int e = blockIdx.x * blockDim.x + threadIdx.x;
    if (e >= Ee) return;
    int d = dst[e];
    int p = atomicAdd(&g_wpos[d], 1);
    g_csr[p] = make_int2(src[e], __float_as_int(attr[e]));
}

// ---------------- dual GEMM body (R14 config; xl stored fp16, xr fp32) --------------
template <int K, bool USE_GH>
__device__ __forceinline__ void gemm_body(const float* __restrict__ X,
                                          const float* __restrict__ pWl,
                                          const float* __restrict__ pWr,
                                          const float* __restrict__ bl,
                                          const float* __restrict__ br,
                                          int bid, int tid) {
    int warp = tid >> 5, lane = tid & 31;
    int row0 = bid * 64 + warp * 8;
    const float* __restrict__ IN = USE_GH ? g_h : X;
    const float2* __restrict__ wl2p = (const float2*)pWl;
    const float2* __restrict__ wr2p = (const float2*)pWr;
    unsigned long long aL[8], aR[8];
    #pragma unroll
    for (int j = 0; j < 8; j++) { aL[j] = 0ull; aR[j] = 0ull; }
    #pragma unroll 2
    for (int k0 = 0; k0 < K; k0 += 4) {
        unsigned long long wl[4], wr[4];
        #pragma unroll
        for (int u = 0; u < 4; u++) {
            float2 a = wl2p[(k0 + u) * 32 + lane]; wl[u] = pack2(a.x, a.y);
            float2 b = wr2p[(k0 + u) * 32 + lane]; wr[u] = pack2(b.x, b.y);
        }
        #pragma unroll
        for (int j = 0; j < 8; j++) {
            int gr = row0 + j;
            float4 xv = (gr < Nn) ? *(const float4*)&IN[gr * K + k0]
                                  : make_float4(0.f, 0.f, 0.f, 0.f);
            unsigned long long x0 = pack2(xv.x, xv.x), x1 = pack2(xv.y, xv.y);
            unsigned long long x2 = pack2(xv.z, xv.z), x3 = pack2(xv.w, xv.w);
            fma2(aL[j], x0, wl[0]); fma2(aR[j], x0, wr[0]);
            fma2(aL[j], x1, wl[1]); fma2(aR[j], x1, wr[1]);
            fma2(aL[j], x2, wl[2]); fma2(aR[j], x2, wr[2]);
            fma2(aL[j], x3, wl[3]); fma2(aR[j], x3, wr[3]);
        }
    }
    float b0 = bl[lane], b1 = bl[lane + 32];
    float c0 = br[lane], c1 = br[lane + 32];
    #pragma unroll
    for (int j = 0; j < 8; j++) {
        int gr = row0 + j;
        if (gr < Nn) {
            float2 l = unpack2(aL[j]);
            float2 r = unpack2(aR[j]); r.x += c0; r.y += c1;
            *(__half2*)&g_xlh[gr * 64 + 2 * lane] =
                __floats2half2_rn(l.x + b0, l.y + b1);
            *(float2*)&g_xr[gr * 64 + 2 * lane] = r;
        }
    }
}

__global__ void gemm1_kernel(const float* __restrict__ X,
                             const float* __restrict__ bl1, const float* __restrict__ br1) {
    gemm_body<Din, false>(X, g_pwl1, g_pwr1, bl1, br1, blockIdx.x, threadIdx.x);
}

__global__ void gemm2_kernel(const float* __restrict__ bl2, const float* __restrict__ br2) {
    gemm_body<Dh, true>(nullptr, g_pwl2, g_pwr2, bl2, br2, blockIdx.x, threadIdx.x);
}

// ---------------- GATv2: 8 lanes/node, 4 nodes/warp, fp16 xl gather -----------------
// One LDG.128 per lane loads all 8 fp16 xl slots (16B); converted to packed f32x2.
// Fixed-reference softmax (anchor = self-loop logit), branchless invalid edges.
__global__ void __launch_bounds__(256) gat_kernel(int layer) {
    int warp = (blockIdx.x * blockDim.x + threadIdx.x) >> 5;
    int lane = threadIdx.x & 31;
    int grp = lane >> 3, seg = lane & 7;
    int node = warp * 4 + grp;
    bool nvalid = node < Nn;
    if (!nvalid) node = Nn - 1;
    int base = node * 64 + seg * 8;

    unsigned long long xr2[4], we2[4], a2[4];
    float at[8];
    {
        float4 v0 = *(const float4*)&g_xr[base];
        float4 v1 = *(const float4*)&g_xr[base + 4];
        xr2[0] = pack2(v0.x, v0.y); xr2[1] = pack2(v0.z, v0.w);
        xr2[2] = pack2(v1.x, v1.y); xr2[3] = pack2(v1.z, v1.w);
        float4 w0 = *(const float4*)&g_pwe[layer * 64 + seg * 8];
        float4 w1 = *(const float4*)&g_pwe[layer * 64 + seg * 8 + 4];
        we2[0] = pack2(w0.x, w0.y); we2[1] = pack2(w0.z, w0.w);
        we2[2] = pack2(w1.x, w1.y); we2[3] = pack2(w1.z, w1.w);
        float4 t0 = *(const float4*)&g_patt[layer * 64 + seg * 8];
        float4 t1 = *(const float4*)&g_patt[layer * 64 + seg * 8 + 4];
        at[0]=t0.x; at[1]=t0.y; at[2]=t0.z; at[3]=t0.w;
        at[4]=t1.x; at[5]=t1.y; at[6]=t1.z; at[7]=t1.w;
    }
    float mean_attr = g_attrsum * (1.0f / Ee);
    int beg = g_indptr[node];
    int deg = g_indptr[node + 1] - beg;

    // ---- self loop first: anchor logit m, a = xl_self, s = 1 ----
    float m, s = 1.f;
    {
        uint4 hv = *(const uint4*)&g_xlh[base];
        a2[0] = h2_to_f2(hv.x); a2[1] = h2_to_f2(hv.y);
        a2[2] = h2_to_f2(hv.z); a2[3] = h2_to_f2(hv.w);
        unsigned long long ma2 = pack2(mean_attr, mean_attr);
        float p = 0.f;
        #pragma unroll
        for (int i = 0; i < 4; i++) {
            unsigned long long t = fma2v(ma2, we2[i], add2(a2[i], xr2[i]));
            float2 u = unpack2(t);
            float l0 = fmaxf(u.x, 0.2f * u.x);
            float l1 = fmaxf(u.y, 0.2f * u.y);
            p = fmaf(l0, at[2 * i], p);
            p = fmaf(l1, at[2 * i + 1], p);
        }
        p += __shfl_xor_sync(FULLMASK, p, 1);
        p += __shfl_xor_sync(FULLMASK, p, 2);
        p += __shfl_xor_sync(FULLMASK, p, 4);
        m = p;
    }

    int tmax = deg;
    tmax = max(tmax, __shfl_xor_sync(FULLMASK, tmax, 8));
    tmax = max(tmax, __shfl_xor_sync(FULLMASK, tmax, 16));

    if (tmax > 0) {
        int2 eA = g_csr[min(beg,     Ee - 1)];
        int2 eB = g_csr[min(beg + 1, Ee - 1)];
        int2 eC = g_csr[min(beg + 2, Ee - 1)];
        unsigned long long xA[4], xB[4];
        {
            uint4 hv = *(const uint4*)&g_xlh[eA.x * 64 + seg * 8];
            xA[0] = h2_to_f2(hv.x); xA[1] = h2_to_f2(hv.y);
            xA[2] = h2_to_f2(hv.z); xA[3] = h2_to_f2(hv.w);
        }
        int t2 = (tmax + 1) & ~1;          // even trip count, pairs (j, j+1)
        for (int j = 0; j < t2; j += 2) {
            {
                uint4 hv = *(const uint4*)&g_xlh[eB.x * 64 + seg * 8];
                xB[0] = h2_to_f2(hv.x); xB[1] = h2_to_f2(hv.y);
                xB[2] = h2_to_f2(hv.z); xB[3] = h2_to_f2(hv.w);
            }
            int2 eD = g_csr[min(beg + j + 3, Ee - 1)];

            {
                float attr = __int_as_float(eA.y);
                unsigned long long at2v = pack2(attr, attr);
                float p = 0.f;
                #pragma unroll
                for (int i = 0; i < 4; i++) {
                    unsigned long long t = fma2v(at2v, we2[i], add2(xA[i], xr2[i]));
                    float2 u = unpack2(t);
                    float l0 = fmaxf(u.x, 0.2f * u.x);
                    float l1 = fmaxf(u.y, 0.2f * u.y);
                    p = fmaf(l0, at[2 * i], p);
                    p = fmaf(l1, at[2 * i + 1], p);
                }
                p += __shfl_xor_sync(FULLMASK, p, 1);
                p += __shfl_xor_sync(FULLMASK, p, 2);
                p += __shfl_xor_sync(FULLMASK, p, 4);
                if (j >= deg) p = -3.0e38f;
                float z = __expf(p - m);
                s += z;
                unsigned long long z2 = pack2(z, z);
                #pragma unroll
                for (int i = 0; i < 4; i++) a2[i] = fma2v(xA[i], z2, a2[i]);
            }

            {
                uint4 hv = *(const uint4*)&g_xlh[eC.x * 64 + seg * 8];
                xA[0] = h2_to_f2(hv.x); xA[1] = h2_to_f2(hv.y);
                xA[2] = h2_to_f2(hv.z); xA[3] = h2_to_f2(hv.w);
            }
            int2 eE = g_csr[min(beg + j + 4, Ee - 1)];

            {
                float attr = __int_as_float(eB.y);
                unsigned long long at2v = pack2(attr, attr);
                float p = 0.f;
                #pragma unroll
                for (int i = 0; i < 4; i++) {
                    unsigned long long t = fma2v(at2v, we2[i], add2(xB[i], xr2[i]));
                    float2 u = unpack2(t);
                    float l0 = fmaxf(u.x, 0.2f * u.x);
                    float l1 = fmaxf(u.y, 0.2f * u.y);
                    p = fmaf(l0, at[2 * i], p);
                    p = fmaf(l1, at[2 * i + 1], p);
                }
                p += __shfl_xor_sync(FULLMASK, p, 1);
                p += __shfl_xor_sync(FULLMASK, p, 2);
                p += __shfl_xor_sync(FULLMASK, p, 4);
                if (j + 1 >= deg) p = -3.0e38f;
                float z = __expf(p - m);
                s += z;
                unsigned long long z2 = pack2(z, z);
                #pragma unroll
                for (int i = 0; i < 4; i++) a2[i] = fma2v(xB[i], z2, a2[i]);
            }

            eA = eC; eB = eD; eC = eE;
        }
    }

    float inv = 1.f / (s + 1e-16f);
    if (nvalid) {
        float o[8];
        #pragma unroll
        for (int i = 0; i < 4; i++) {
            float2 u = unpack2(a2[i]);
            float v0 = fmaf(u.x, inv, g_pbias[layer * 64 + seg * 8 + 2 * i]);
            float v1 = fmaf(u.y, inv, g_pbias[layer * 64 + seg * 8 + 2 * i + 1]);
            o[2 * i]     = v0 > 0.f ? v0 : expm1f(v0);   // ELU
            o[2 * i + 1] = v1 > 0.f ? v1 : expm1f(v1);
        }
        float4* hp = (float4*)&g_h[base];
        hp[0] = make_float4(o[0], o[1], o[2], o[3]);
        hp[1] = make_float4(o[4], o[5], o[6], o[7]);
    }
}

// ---------------- mean pool per graph (batch sorted; storage-order dims) -----------
__global__ void pool_kernel(const int* __restrict__ batch) {
    int d = threadIdx.x;                 // 64 threads = 64 storage slots
    int n0 = blockIdx.x * 256;
    int n1 = n0 + 256; if (n1 > Nn) n1 = Nn;
    float acc = 0.f; int curg = -1; int c = 0;
    for (int n = n0; n < n1; ++n) {
        int g = batch[n];
        if (g != curg) {
            if (curg >= 0) {
                atomicAdd(&g_pooled[curg * Dh + d], acc);
                if (d == 0) atomicAdd(&g_cnt[curg], c);
            }
            curg = g; acc = 0.f; c = 0;
        }
        acc += g_h[n * Dh + d];
        ++c;
    }
    if (curg >= 0) {
        atomicAdd(&g_pooled[curg * Dh + d], acc);
        if (d == 0) atomicAdd(&g_cnt[curg], c);
    }
}

// ---------------- classifier (un-permutes storage -> dim) ----------------
__global__ void cls_kernel(const float* __restrict__ Wc, const float* __restrict__ bc,
                           float* __restrict__ out) {
    int t = threadIdx.x;                 // 640 threads
    int g = t / NCLS, c = t - g * NCLS;
    float invc = 1.f / fmaxf((float)g_cnt[g], 1.f);
    float acc = bc[c];
    #pragma unroll 8
    for (int s = 0; s < Dh; ++s) {
        int d = (s >> 1) + ((s & 1) << 5);     // storage slot -> true dim
        acc += g_pooled[g * Dh + s] * invc * Wc[d * NCLS + c];
    }
    out[t] = acc;
}

// ---------------- launch: forked-graph two-branch pipeline ----------------
extern "C" void kernel_launch(void* const* d_in, const int* in_sizes, int n_in,
                              void* d_out, int out_size) {
    const float* x    = (const float*)d_in[0];
    const int*   ei   = (const int*)  d_in[1];
    const float* eatt = (const float*)d_in[2];
    const int*   batch= (const int*)  d_in[3];
    const float* Wl1 = (const float*)d_in[4],  *bl1 = (const float*)d_in[5];
    const float* Wr1 = (const float*)d_in[6],  *br1 = (const float*)d_in[7];
    const float* We1 = (const float*)d_in[8],  *att1= (const float*)d_in[9];
    const float* b1  = (const float*)d_in[10];
    const float* Wl2 = (const float*)d_in[11], *bl2 = (const float*)d_in[12];
    const float* Wr2 = (const float*)d_in[13], *br2 = (const float*)d_in[14];
    const float* We2 = (const float*)d_in[15], *att2= (const float*)d_in[16];
    const float* b2  = (const float*)d_in[17];
    const float* Wc  = (const float*)d_in[18], *bc  = (const float*)d_in[19];
    float* out = (float*)d_out;

    const int* src = ei;
    const int* dst = ei + Ee;

    int gat_blocks = (Nn / 4 + 7) / 8 + 1;   // warps of 4 nodes, 8 warps/block

    // fork resources (created per call; NOT destroyed — a forked stream must
    // outlive the capture. kernel_launch runs only twice, so this leaks 2
    // streams + 4 events total: host-side, no device memory.)
    cudaStream_t s2;
    cudaStreamCreateWithFlags(&s2, cudaStreamNonBlocking);
    cudaEvent_t eFork, eJoin;
    cudaEventCreateWithFlags(&eFork, cudaEventDisableTiming);
    cudaEventCreateWithFlags(&eJoin, cudaEventDisableTiming);

    // fork: side branch roots at capture start
    cudaEventRecord(eFork, 0);
    cudaStreamWaitEvent(s2, eFork, 0);

    // branch B (side stream): weight permute -> gemm1 (writes g_xlh/g_xr)
    initB_kernel<<<49, 256, 0, s2>>>(Wl1, Wr1, Wl2, Wr2, We1, att1, b1, We2, att2, b2);
    gemm1_kernel<<<GEMM1_BLOCKS, 256, 0, s2>>>(x, bl1, br1);
    cudaEventRecord(eJoin, s2);

    // branch A (main stream): zero+count -> scan -> scatter (writes g_csr)
    initA_kernel<<<196 + COUNT_BLOCKS, 256>>>(dst, eatt);
    scan_kernel<<<NBLK, 1024>>>();
    scatter_kernel<<<SCAT_BLOCKS, 256>>>(src, dst, eatt);

    // join: gat needs both g_csr (A) and g_xlh/g_xr (B)
    cudaStreamWaitEvent(0, eJoin, 0);

    gat_kernel<<<gat_blocks, 256>>>(0);
    gemm2_kernel<<<GEMM1_BLOCKS, 256>>>(bl2, br2);
    gat_kernel<<<gat_blocks, 256>>>(1);
    pool_kernel<<<(Nn + 255) / 256, 64>>>(batch);
    cls_kernel<<<1, Gg * NCLS>>>(Wc, bc, out);
}